// round 14
// baseline (speedup 1.0000x reference)
#include <cuda_runtime.h>
#include <cuda_bf16.h>
#include <math.h>

// Problem shapes (fixed by the dataset)
#define B_  4096
#define L_  200
#define D_  256
#define BN_EPS 1e-5f

// -------- scratch (no allocations allowed) --------
__device__ float g_pp[2 * B_ * D_];          // 8 MB: per-half partial sums
__device__ float g_z[B_ * D_];               // 4 MB
__device__ float g_part[2 * 128 * D_];       // per-32-row-tile col sums/sumsq
__device__ float g_lossp[256];               // per-head-block loss partials
__device__ unsigned int g_ticket;            // monotonic last-block ticket

// float -> tf32 (round to nearest, bit pattern in u32)
__device__ __forceinline__ unsigned int f2tf32(float f)
{
    unsigned int u;
    asm("cvt.rna.tf32.f32 %0, %1;" : "=r"(u) : "f"(f));
    return u;
}

// emb load: non-coherent, L2 evict_last policy (keep table resident)
__device__ __forceinline__ float4 ldg_keep(const float4* p, unsigned long long pol)
{
    float4 v;
    asm volatile("ld.global.nc.L2::cache_hint.v4.f32 {%0,%1,%2,%3}, [%4], %5;"
                 : "=f"(v.x), "=f"(v.y), "=f"(v.z), "=f"(v.w)
                 : "l"(p), "l"(pol));
    return v;
}

// ============================================================
// Kernel 1: ragged gather partial-pool (EXACT R8 best: 33.7us).
// 1 block = (row, token-half). 8192 blocks x 64 threads.
// ============================================================
__global__ void __launch_bounds__(64) pool_kernel(
    const int* __restrict__ tokens,
    const int* __restrict__ lengths,
    const float* __restrict__ emb)
{
    const int bid  = blockIdx.x;
    const int row  = bid >> 1;
    const int half = bid & 1;
    const int tid  = threadIdx.x;
    __shared__ int s_tok[104];

    unsigned long long pol;
    asm("createpolicy.fractional.L2::evict_last.b64 %0, 1.0;" : "=l"(pol));

    const int len   = lengths[row];
    const int n0    = len >> 1;
    const int start = half ? n0 : 0;
    const int cnt   = half ? (len - n0) : n0;

    for (int i = tid; i < cnt; i += 64)
        s_tok[i] = __ldcs(&tokens[row * L_ + start + i]);
    __syncthreads();

    const float4* __restrict__ emb4 = (const float4*)emb;  // row stride 64

    float4 a0 = make_float4(0.f, 0.f, 0.f, 0.f);
    float4 a1 = make_float4(0.f, 0.f, 0.f, 0.f);
    int l = 0;
    for (; l + 8 <= cnt; l += 8) {
        float4 v0 = ldg_keep(&emb4[(size_t)s_tok[l + 0] * 64 + tid], pol);
        float4 v1 = ldg_keep(&emb4[(size_t)s_tok[l + 1] * 64 + tid], pol);
        float4 v2 = ldg_keep(&emb4[(size_t)s_tok[l + 2] * 64 + tid], pol);
        float4 v3 = ldg_keep(&emb4[(size_t)s_tok[l + 3] * 64 + tid], pol);
        float4 v4 = ldg_keep(&emb4[(size_t)s_tok[l + 4] * 64 + tid], pol);
        float4 v5 = ldg_keep(&emb4[(size_t)s_tok[l + 5] * 64 + tid], pol);
        float4 v6 = ldg_keep(&emb4[(size_t)s_tok[l + 6] * 64 + tid], pol);
        float4 v7 = ldg_keep(&emb4[(size_t)s_tok[l + 7] * 64 + tid], pol);
        a0.x += (v0.x + v1.x) + (v2.x + v3.x);
        a0.y += (v0.y + v1.y) + (v2.y + v3.y);
        a0.z += (v0.z + v1.z) + (v2.z + v3.z);
        a0.w += (v0.w + v1.w) + (v2.w + v3.w);
        a1.x += (v4.x + v5.x) + (v6.x + v7.x);
        a1.y += (v4.y + v5.y) + (v6.y + v7.y);
        a1.z += (v4.z + v5.z) + (v6.z + v7.z);
        a1.w += (v4.w + v5.w) + (v6.w + v7.w);
    }
    for (; l < cnt; ++l) {
        float4 v = ldg_keep(&emb4[(size_t)s_tok[l] * 64 + tid], pol);
        a0.x += v.x; a0.y += v.y; a0.z += v.z; a0.w += v.w;
    }
    float4 o;
    o.x = a0.x + a1.x; o.y = a0.y + a1.y;
    o.z = a0.z + a1.z; o.w = a0.w + a1.w;
    __stcs(&((float4*)g_pp)[((size_t)half * B_ + row) * 64 + tid], o);
}

// ============================================================
// Kernel 2: tf32 GEMM, BM=32 x BN=64 tiles -> grid (4,128) = 512
// blocks, 256 threads, inline pp combine. Fused stats epilogue
// into g_part (128 row-groups). No grid sync -> full occupancy.
// Warp map: wm = warp>>2 (2 x m16), wn = warp&3 (4 x n16 = 2 x n8).
// ============================================================
__global__ void __launch_bounds__(256, 3) gemm_kernel(
    const int*   __restrict__ lengths,
    const float* __restrict__ W,
    const float* __restrict__ b1,
    float* __restrict__ Z)
{
    __shared__ union {
        struct {
            unsigned int As_u[32][68];   //  8704 B
            unsigned int Bs_u[64][68];   // 17408 B
            float s_inv[32];
        } g;
        struct {
            float rs[16 * 65];           // 4160 B  (inside As region)
            float rss[16 * 65];          // 4160 B
        } r;
    } sm;

    const int tid  = threadIdx.x;
    const int lane = tid & 31;
    const int warp = tid >> 5;
    const int g    = lane >> 2;          // 0..7
    const int tq   = lane & 3;           // 0..3
    const int wm   = warp >> 2;          // 0..1 -> m offset 16*wm
    const int wn   = warp & 3;           // 0..3 -> n offset 16*wn
    const int by   = blockIdx.y;         // 0..127
    const int bm   = by * 32;
    const int bn   = blockIdx.x * 64;

    if (tid < 32) sm.g.s_inv[tid] = 1.f / (float)lengths[bm + tid];
    __syncthreads();

    const float4* __restrict__ pp4 = (const float4*)g_pp;

    float c[2][4] = {};   // c[nb][0..3]: rows {g,g,g+8,g+8}, cols {2tq,2tq+1}

    for (int k0 = 0; k0 < D_; k0 += 64) {
        // ---- load A tile 32x64 (combine pp halves, /len, ->tf32) ----
        #pragma unroll
        for (int j = 0; j < 2; ++j) {
            int idx = tid + j * 256;       // 0..511
            int m   = idx >> 4;            // 0..31
            int k4  = idx & 15;            // 0..15
            int fi  = (k0 >> 2) + k4;
            float4 p0 = __ldg(&pp4[(size_t)(bm + m) * 64 + fi]);
            float4 p1 = __ldg(&pp4[((size_t)B_ + bm + m) * 64 + fi]);
            float inv = sm.g.s_inv[m];
            uint4 ua;
            ua.x = f2tf32((p0.x + p1.x) * inv);
            ua.y = f2tf32((p0.y + p1.y) * inv);
            ua.z = f2tf32((p0.z + p1.z) * inv);
            ua.w = f2tf32((p0.w + p1.w) * inv);
            *(uint4*)&sm.g.As_u[m][k4 * 4] = ua;
        }
        // ---- load W tile 64x64 -> tf32 ----
        #pragma unroll
        for (int j = 0; j < 4; ++j) {
            int idx = tid + j * 256;       // 0..1023
            int m   = idx >> 4;            // 0..63
            int k4  = idx & 15;
            float4 vb = *(const float4*)&W[(size_t)(bn + m) * D_ + k0 + k4 * 4];
            uint4 ub;
            ub.x = f2tf32(vb.x); ub.y = f2tf32(vb.y);
            ub.z = f2tf32(vb.z); ub.w = f2tf32(vb.w);
            *(uint4*)&sm.g.Bs_u[m][k4 * 4] = ub;
        }
        __syncthreads();

        const int am = wm * 16 + g;
        #pragma unroll
        for (int ks = 0; ks < 8; ++ks) {
            const int kc = ks * 8;
            unsigned int a0 = sm.g.As_u[am    ][kc + tq];
            unsigned int a1 = sm.g.As_u[am + 8][kc + tq];
            unsigned int a2 = sm.g.As_u[am    ][kc + tq + 4];
            unsigned int a3 = sm.g.As_u[am + 8][kc + tq + 4];
            #pragma unroll
            for (int nb = 0; nb < 2; ++nb) {
                const int bnrow = wn * 16 + nb * 8 + g;
                unsigned int b0  = sm.g.Bs_u[bnrow][kc + tq];
                unsigned int b1r = sm.g.Bs_u[bnrow][kc + tq + 4];
                asm volatile(
                    "mma.sync.aligned.m16n8k8.row.col.f32.tf32.tf32.f32 "
                    "{%0,%1,%2,%3}, {%4,%5,%6,%7}, {%8,%9}, {%0,%1,%2,%3};"
                    : "+f"(c[nb][0]), "+f"(c[nb][1]),
                      "+f"(c[nb][2]), "+f"(c[nb][3])
                    : "r"(a0), "r"(a1), "r"(a2), "r"(a3),
                      "r"(b0), "r"(b1r));
            }
        }
        __syncthreads();
    }

    // ---------------- epilogue: bias + Z store + fused stats -------------
    const int row0 = bm + wm * 16 + g;       // and row0+8
    float colsum[4], colsq[4];

    #pragma unroll
    for (int nb = 0; nb < 2; ++nb) {
        const int col = bn + wn * 16 + nb * 8 + 2 * tq;
        const float bz0 = b1[col], bz1 = b1[col + 1];
        float v00 = c[nb][0] + bz0, v01 = c[nb][1] + bz1;   // row0
        float v10 = c[nb][2] + bz0, v11 = c[nb][3] + bz1;   // row0+8
        *(float2*)&Z[(size_t)row0 * D_ + col]       = make_float2(v00, v01);
        *(float2*)&Z[(size_t)(row0 + 8) * D_ + col] = make_float2(v10, v11);
        colsum[nb * 2 + 0] = v00 + v10;
        colsum[nb * 2 + 1] = v01 + v11;
        colsq [nb * 2 + 0] = fmaf(v00, v00, v10 * v10);
        colsq [nb * 2 + 1] = fmaf(v01, v01, v11 * v11);
    }

    // stats: 16 contributors (wm*8+g) per column, stride 65
    const int contrib = wm * 8 + g;
    #pragma unroll
    for (int nb = 0; nb < 2; ++nb) {
        #pragma unroll
        for (int j = 0; j < 2; ++j) {
            int lc = wn * 16 + nb * 8 + 2 * tq + j;
            sm.r.rs [contrib * 65 + lc] = colsum[nb * 2 + j];
            sm.r.rss[contrib * 65 + lc] = colsq [nb * 2 + j];
        }
    }
    __syncthreads();
    if (tid < 64) {
        float s = 0.f, ssq = 0.f;
        #pragma unroll
        for (int i = 0; i < 16; ++i) {
            s   += sm.r.rs [i * 65 + tid];
            ssq += sm.r.rss[i * 65 + tid];
        }
        g_part[(size_t)by * D_ + bn + tid]            = s;
        g_part[128 * D_ + (size_t)by * D_ + bn + tid] = ssq;
    }
}

// ============================================================
// Kernel 3: BN finalize + BN+ReLU+dot(w2)+BCE + ticketed loss.
// grid 256 x 256 threads; block = 16 rows; warp = 2 rows.
// ============================================================
__global__ void __launch_bounds__(256) head_kernel(
    const float* __restrict__ Z,
    const float* __restrict__ gamma,
    const float* __restrict__ beta,
    const float* __restrict__ w2,
    const float* __restrict__ b2,
    const float* __restrict__ t,
    float* __restrict__ out)
{
    const int tid  = threadIdx.x;
    const int lane = tid & 31;
    const int warp = tid >> 5;
    const int bid  = blockIdx.x;

    __shared__ float s_g[D_], s_be[D_], s_w[D_];
    __shared__ float red[8];
    __shared__ int s_last;

    // Phase 1: finalize BN stats for dim d = tid (128 row-groups)
    {
        float sm = 0.f, sq = 0.f;
        #pragma unroll 16
        for (int rb = 0; rb < 128; ++rb) {
            sm += g_part[(size_t)rb * D_ + tid];
            sq += g_part[128 * D_ + (size_t)rb * D_ + tid];
        }
        float mu   = sm * (1.f / (float)B_);
        float var  = sq * (1.f / (float)B_) - mu * mu;
        float rstd = rsqrtf(var + BN_EPS);
        float g    = gamma[tid] * rstd;
        s_g[tid]  = g;
        s_be[tid] = beta[tid] - g * mu;
        s_w[tid]  = w2[tid];
    }
    __syncthreads();

    // Phase 2: 2 rows per warp
    const int row0 = bid * 16 + warp * 2;
    const float b2v = b2[0];

    float acc[2] = {0.f, 0.f};
    #pragma unroll
    for (int k = 0; k < 8; ++k) {
        int dm = lane + 32 * k;
        float gk = s_g[dm], bek = s_be[dm], wk = s_w[dm];
        #pragma unroll
        for (int r = 0; r < 2; ++r) {
            float zv = Z[(size_t)(row0 + r) * D_ + dm];
            acc[r] += fmaxf(fmaf(gk, zv, bek), 0.f) * wk;
        }
    }
    #pragma unroll
    for (int off = 16; off > 0; off >>= 1) {
        acc[0] += __shfl_xor_sync(0xFFFFFFFFu, acc[0], off);
        acc[1] += __shfl_xor_sync(0xFFFFFFFFu, acc[1], off);
    }

    if (lane == 0) {
        float lossacc = 0.f;
        #pragma unroll
        for (int r = 0; r < 2; ++r) {
            float l = acc[r] + b2v;
            out[1 + row0 + r] = l;
            float tb = t[row0 + r];
            lossacc += fmaxf(l, 0.f) - l * tb + log1pf(expf(-fabsf(l)));
        }
        red[warp] = lossacc;
    }
    __syncthreads();

    // per-block loss partial + last-block election (monotonic ticket)
    if (tid == 0) {
        float sum = 0.f;
        #pragma unroll
        for (int w = 0; w < 8; ++w) sum += red[w];
        g_lossp[bid] = sum;
        __threadfence();
        unsigned int my = atomicAdd(&g_ticket, 1u);
        s_last = ((my + 1u) & 255u) == 0u;   // last of this replay's 256
    }
    __syncthreads();

    if (s_last) {
        __threadfence();
        if (warp == 0) {
            float v = 0.f;
            #pragma unroll
            for (int j = 0; j < 8; ++j)
                v += g_lossp[lane + 32 * j];
            #pragma unroll
            for (int off = 16; off > 0; off >>= 1)
                v += __shfl_xor_sync(0xFFFFFFFFu, v, off);
            if (lane == 0) out[0] = v * (1.f / (float)B_);
        }
    }
}

// ============================================================
// launch: 3 kernels, serial
// ============================================================
extern "C" void kernel_launch(void* const* d_in, const int* in_sizes, int n_in,
                              void* d_out, int out_size)
{
    const int*   tokens  = (const int*)d_in[0];
    const int*   lengths = (const int*)d_in[1];
    const float* t       = (const float*)d_in[2];
    const float* emb     = (const float*)d_in[3];
    const float* W1      = (const float*)d_in[4];
    const float* b1      = (const float*)d_in[5];
    const float* gamma   = (const float*)d_in[6];
    const float* beta    = (const float*)d_in[7];
    const float* w2      = (const float*)d_in[8];
    const float* b2      = (const float*)d_in[9];
    float* out = (float*)d_out;

    float* z; cudaGetSymbolAddress((void**)&z, g_z);

    pool_kernel<<<B_ * 2, 64>>>(tokens, lengths, emb);

    dim3 ggrid(D_ / 64, B_ / 32);   // (4, 128) = 512 blocks
    gemm_kernel<<<ggrid, 256>>>(lengths, W1, b1, z);

    head_kernel<<<B_ / 16, 256>>>(z, gamma, beta, w2, b2, t, out);
}